// round 13
// baseline (speedup 1.0000x reference)
#include <cuda_runtime.h>
#include <cuda_fp16.h>
#include <cstdint>

#define NUM_USERS 30000
#define NUM_ITEMS 70000
#define NTOT      100000
#define D         128
#define NNZ       1000000
#define NLAYERS   3
#define BATCH     16384
#define FD        512   // D * (1 + NLAYERS)

#define SCAN_BS   1024
#define SCAN_NB   ((NTOT + SCAN_BS - 1) / SCAN_BS)  // 98

// Scratch (no cudaMalloc allowed)
__device__ float  g_final[(size_t)NTOT * FD];
__device__ int    g_cnt[NTOT];
__device__ int    g_start[NTOT + 1];
__device__ int    g_cursor[NTOT];
__device__ int    g_ecol[NNZ];
__device__ float  g_eval[NNZ];
__device__ int    g_bsum[SCAN_NB];
__device__ int    g_boff[SCAN_NB];
// Pre-transposed fp16 weight images: per (layer, phase{lin,int}): B[n][k]=W[k][n], 8192 u32 (32KB)
__device__ uint32_t g_wimg[3 * 2 * 8192];

// ======================= mma.sync helpers =======================
__device__ __forceinline__ uint32_t smem_u32(const void* p) {
    uint32_t a;
    asm("{ .reg .u64 t; cvta.to.shared.u64 t, %1; cvt.u32.u64 %0, t; }" : "=r"(a) : "l"(p));
    return a;
}
__device__ __forceinline__ void ldsm4(uint32_t* r, uint32_t addr) {
    asm volatile("ldmatrix.sync.aligned.m8n8.x4.shared.b16 {%0,%1,%2,%3}, [%4];"
                 : "=r"(r[0]), "=r"(r[1]), "=r"(r[2]), "=r"(r[3]) : "r"(addr));
}
__device__ __forceinline__ void mma16816h(float* d, const uint32_t* a, uint32_t b0, uint32_t b1) {
    asm volatile(
        "mma.sync.aligned.m16n8k16.row.col.f32.f16.f16.f32 "
        "{%0,%1,%2,%3}, {%4,%5,%6,%7}, {%8,%9}, {%0,%1,%2,%3};"
        : "+f"(d[0]), "+f"(d[1]), "+f"(d[2]), "+f"(d[3])
        : "r"(a[0]), "r"(a[1]), "r"(a[2]), "r"(a[3]), "r"(b0), "r"(b1));
}

#define TPITCH_B 272
#define MTILE    64
#define ATILE_B  (MTILE * TPITCH_B)   // 17408
#define BTILE_B  (128 * TPITCH_B)     // 34816
#define NTHR     512                  // 8 consumer warps + 8 producer warps
#define NSM      148
#define NTILES   ((NTOT + MTILE - 1) / MTILE)   // 1563

// ---------------------------------------------------------------------------
// Init: features slice 0 + zero g_cnt (fused)
// ---------------------------------------------------------------------------
__global__ void k_init(const float* __restrict__ uE, const float* __restrict__ iE) {
    int idx = blockIdx.x * blockDim.x + threadIdx.x;
    const int total = NTOT * (D / 4);
    if (idx < total) {
        int r = idx >> 5;
        int q = idx & 31;
        float4 v = (r < NUM_USERS)
            ? ((const float4*)uE)[(size_t)r * (D / 4) + q]
            : ((const float4*)iE)[(size_t)(r - NUM_USERS) * (D / 4) + q];
        ((float4*)g_final)[(size_t)r * (FD / 4) + q] = v;
    }
    if (idx < NTOT) g_cnt[idx] = 0;
}

// ---------------------------------------------------------------------------
// Weight transpose+fp16 precompute (once). B[n][k] = W[k][n].
// ---------------------------------------------------------------------------
__global__ void k_wconv(const float* __restrict__ Wlin, const float* __restrict__ Wint) {
    int idx = blockIdx.x * blockDim.x + threadIdx.x;
    const int total = 3 * 2 * 128 * 64;
    if (idx >= total) return;
    int k2 = idx & 63;
    int n  = (idx >> 6) & 127;
    int lp = idx >> 13;
    int p  = lp & 1;
    int l  = lp >> 1;
    int k  = k2 * 2;
    const float* W = (p ? Wint : Wlin) + (size_t)l * D * D;
    __half2 h = __floats2half2_rn(W[(size_t)k * 128 + n], W[(size_t)(k + 1) * 128 + n]);
    g_wimg[(size_t)(l * 2 + p) * 8192 + n * 64 + k2] = *(uint32_t*)&h;
}

// ---------------------------------------------------------------------------
// CSR build
// ---------------------------------------------------------------------------
__global__ void k_count(const int* __restrict__ rows) {
    int e = blockIdx.x * blockDim.x + threadIdx.x;
    if (e < NNZ) atomicAdd(&g_cnt[rows[e]], 1);
}
__global__ void k_scan1() {
    __shared__ int wsum[8];
    int t = threadIdx.x;
    int base = blockIdx.x * SCAN_BS + t * 4;
    int c0 = 0, c1 = 0, c2 = 0, c3 = 0;
    if (base + 3 < NTOT) {
        int4 c = *(const int4*)(g_cnt + base);
        c0 = c.x; c1 = c.y; c2 = c.z; c3 = c.w;
    } else {
        if (base + 0 < NTOT) c0 = g_cnt[base + 0];
        if (base + 1 < NTOT) c1 = g_cnt[base + 1];
        if (base + 2 < NTOT) c2 = g_cnt[base + 2];
        if (base + 3 < NTOT) c3 = g_cnt[base + 3];
    }
    int tot = c0 + c1 + c2 + c3;
    int inc = tot;
    #pragma unroll
    for (int d = 1; d < 32; d <<= 1) {
        int v = __shfl_up_sync(0xffffffffu, inc, d);
        if ((t & 31) >= d) inc += v;
    }
    if ((t & 31) == 31) wsum[t >> 5] = inc;
    __syncthreads();
    if (t < 8) {
        int v = wsum[t];
        int wi = v;
        #pragma unroll
        for (int d = 1; d < 8; d <<= 1) {
            int u = __shfl_up_sync(0xffu, wi, d);
            if (t >= d) wi += u;
        }
        wsum[t] = wi - v;
        if (t == 7) g_bsum[blockIdx.x] = wi;
    }
    __syncthreads();
    int off = wsum[t >> 5] + (inc - tot);
    if (base + 0 < NTOT) g_start[base + 0] = off;
    if (base + 1 < NTOT) g_start[base + 1] = off + c0;
    if (base + 2 < NTOT) g_start[base + 2] = off + c0 + c1;
    if (base + 3 < NTOT) g_start[base + 3] = off + c0 + c1 + c2;
}
__global__ void k_scan2() {
    __shared__ int wsum[4];
    int t = threadIdx.x;
    int v = (t < SCAN_NB) ? g_bsum[t] : 0;
    int inc = v;
    #pragma unroll
    for (int d = 1; d < 32; d <<= 1) {
        int u = __shfl_up_sync(0xffffffffu, inc, d);
        if ((t & 31) >= d) inc += u;
    }
    if ((t & 31) == 31) wsum[t >> 5] = inc;
    __syncthreads();
    if (t < 4) {
        int w = wsum[t];
        int wi = w;
        #pragma unroll
        for (int d = 1; d < 4; d <<= 1) {
            int u = __shfl_up_sync(0xfu, wi, d);
            if (t >= d) wi += u;
        }
        wsum[t] = wi - w;
    }
    __syncthreads();
    if (t < SCAN_NB) g_boff[t] = wsum[t >> 5] + (inc - v);
    if (t == 0) g_start[NTOT] = NNZ;
}
__global__ void k_scan3() {
    int i = blockIdx.x * blockDim.x + threadIdx.x;
    if (i >= NTOT) return;
    int s = g_start[i] + g_boff[i / SCAN_BS];
    g_start[i] = s;
    g_cursor[i] = s;
}
__global__ void k_scatter(const int* __restrict__ rows, const int* __restrict__ cols,
                          const float* __restrict__ vals) {
    int e = blockIdx.x * blockDim.x + threadIdx.x;
    if (e >= NNZ) return;
    int p = atomicAdd(&g_cursor[rows[e]], 1);
    g_ecol[p] = cols[e];
    g_eval[p] = vals[e];
}

// ---------------------------------------------------------------------------
// Fused persistent SpMM + dual-GEMM, warp-specialized.
// Grid=148, 512 threads. Warps 0-7: MMA consumers (64x128 tile, 2Mx4N warp
// grid). Warps 8-15: gather producers — CSR SpMM for the NEXT tile's 64 rows,
// fused with the (Lx+f)/(Lx*f) fp16 conversion, written straight into the
// alternate A buffer. B images resident all kernel. One __syncthreads per
// pipeline stage (both role branches execute the same count).
// smem: 2x34KB B + 2x(S,P) 17KB A buffers = 136KB -> 1 CTA/SM.
// ---------------------------------------------------------------------------
__global__ void __launch_bounds__(NTHR) k_fused(const float* __restrict__ blin,
                                                const float* __restrict__ bint,
                                                int layer) {
    extern __shared__ char dsm[];
    __shared__ float sPart[MTILE][4];
    __shared__ float sBias[128];

    char* sBlin = dsm;
    char* sBint = dsm + BTILE_B;
    char* sA    = dsm + 2 * BTILE_B;    // [buf][{S,P}] each ATILE_B
    uint32_t uBase = smem_u32(dsm);
    uint32_t uBlin = uBase;
    uint32_t uBint = uBase + BTILE_B;
    uint32_t uA    = uBase + 2 * BTILE_B;

    int tid = threadIdx.x;
    int wid = tid >> 5;
    int lane = tid & 31;

    // ---- Prologue: B images + bias (all threads) ----
    {
        const uint32_t* srcL = g_wimg + (size_t)(layer * 2 + 0) * 8192;
        const uint32_t* srcI = g_wimg + (size_t)(layer * 2 + 1) * 8192;
        for (int i = tid; i < 2048; i += NTHR) {
            int n = i >> 4;
            int jj = i & 15;
            *(uint4*)(sBlin + n * TPITCH_B + jj * 16) = ((const uint4*)(srcL + n * 64))[jj];
            *(uint4*)(sBint + n * TPITCH_B + jj * 16) = ((const uint4*)(srcI + n * 64))[jj];
        }
        if (tid < 128)
            sBias[tid] = __ldg(blin + (size_t)layer * D + tid) + __ldg(bint + (size_t)layer * D + tid);
    }

    int nTiles = 0;
    for (int t = blockIdx.x; t < NTILES; t += NSM) nTiles++;

    const float* fslice = g_final + (size_t)layer * D;   // gather plane, row stride FD

    if (wid >= 8) {
        // ================= PRODUCER: SpMM gather + fp16 convert =================
        int pw = wid - 8;   // 0..7 -> rows [8*pw, 8*pw+8)
        for (int i = 0; i < nTiles + 1; i++) {
            if (i < nTiles) {
                int rbase = (blockIdx.x + i * NSM) * MTILE;
                char* sS = sA + (size_t)(i & 1) * 2 * ATILE_B;
                char* sP = sS + ATILE_B;
                #pragma unroll 1
                for (int m = pw * 8; m < pw * 8 + 8; m++) {
                    int r = rbase + m;
                    float4 acc = make_float4(0.f, 0.f, 0.f, 0.f);
                    float4 f   = make_float4(0.f, 0.f, 0.f, 0.f);
                    if (r < NTOT) {
                        int s = g_start[r];
                        int e = g_start[r + 1];
                        for (int base = s; base < e; base += 32) {
                            int idx = base + lane;
                            int c = 0; float v = 0.f;
                            if (idx < e) { c = g_ecol[idx]; v = g_eval[idx]; }
                            int cnt = min(32, e - base);
                            int j = 0;
                            for (; j + 4 <= cnt; j += 4) {
                                int   c0 = __shfl_sync(0xffffffffu, c, j + 0);
                                int   c1 = __shfl_sync(0xffffffffu, c, j + 1);
                                int   c2 = __shfl_sync(0xffffffffu, c, j + 2);
                                int   c3 = __shfl_sync(0xffffffffu, c, j + 3);
                                float v0 = __shfl_sync(0xffffffffu, v, j + 0);
                                float v1 = __shfl_sync(0xffffffffu, v, j + 1);
                                float v2 = __shfl_sync(0xffffffffu, v, j + 2);
                                float v3 = __shfl_sync(0xffffffffu, v, j + 3);
                                float4 x0 = ((const float4*)(fslice + (size_t)c0 * FD))[lane];
                                float4 x1 = ((const float4*)(fslice + (size_t)c1 * FD))[lane];
                                float4 x2 = ((const float4*)(fslice + (size_t)c2 * FD))[lane];
                                float4 x3 = ((const float4*)(fslice + (size_t)c3 * FD))[lane];
                                acc.x += v0 * x0.x + v1 * x1.x + v2 * x2.x + v3 * x3.x;
                                acc.y += v0 * x0.y + v1 * x1.y + v2 * x2.y + v3 * x3.y;
                                acc.z += v0 * x0.z + v1 * x1.z + v2 * x2.z + v3 * x3.z;
                                acc.w += v0 * x0.w + v1 * x1.w + v2 * x2.w + v3 * x3.w;
                            }
                            for (; j < cnt; j++) {
                                int   cj = __shfl_sync(0xffffffffu, c, j);
                                float vj = __shfl_sync(0xffffffffu, v, j);
                                float4 x = ((const float4*)(fslice + (size_t)cj * FD))[lane];
                                acc.x += vj * x.x; acc.y += vj * x.y;
                                acc.z += vj * x.z; acc.w += vj * x.w;
                            }
                        }
                        f = ((const float4*)(g_final + (size_t)r * FD + (size_t)layer * D))[lane];
                    }
                    // convert: S = acc+f, P = acc*f -> fp16 pairs
                    __half2 h;
                    uint2 sv, pv;
                    h = __floats2half2_rn(acc.x + f.x, acc.y + f.y); sv.x = *(uint32_t*)&h;
                    h = __floats2half2_rn(acc.z + f.z, acc.w + f.w); sv.y = *(uint32_t*)&h;
                    h = __floats2half2_rn(acc.x * f.x, acc.y * f.y); pv.x = *(uint32_t*)&h;
                    h = __floats2half2_rn(acc.z * f.z, acc.w * f.w); pv.y = *(uint32_t*)&h;
                    int off = m * TPITCH_B + lane * 8;   // cols 4*lane..4*lane+3
                    *(uint2*)(sS + off) = sv;
                    *(uint2*)(sP + off) = pv;
                }
            }
            __syncthreads();
        }
    } else {
        // ================= CONSUMER: MMA mainloop + epilogue =================
        int wm = wid & 1, wn = wid >> 1;    // 2(M) x 4(N)
        int m0 = wm * 32, n0 = wn * 32;
        int g = lane >> 2, t4 = lane & 3;

        int aRow = m0 + (lane & 15);
        uint32_t aOff0 = (uint32_t)(aRow * TPITCH_B + (lane >> 4) * 16);
        uint32_t aOff1 = aOff0 + 16 * TPITCH_B;
        int bRow = n0 + ((lane >> 4) << 3) + (lane & 7);
        uint32_t bOff0 = (uint32_t)(bRow * TPITCH_B + ((lane >> 3) & 1) * 16);
        uint32_t bOff1 = bOff0 + 16 * TPITCH_B;

        for (int i = 0; i < nTiles + 1; i++) {
            if (i > 0) {
                int rbase = (blockIdx.x + (i - 1) * NSM) * MTILE;
                uint32_t uS = uA + (uint32_t)((i - 1) & 1) * 2 * ATILE_B;

                float c[2][4][4];
                #pragma unroll
                for (int mt = 0; mt < 2; mt++)
                    #pragma unroll
                    for (int j = 0; j < 4; j++)
                        #pragma unroll
                        for (int q = 0; q < 4; q++) c[mt][j][q] = 0.f;

                #pragma unroll
                for (int phase = 0; phase < 2; phase++) {
                    uint32_t uAcur = uS + phase * ATILE_B;
                    uint32_t uBcur = phase ? uBint : uBlin;
                    #pragma unroll
                    for (int ks = 0; ks < 8; ks++) {
                        uint32_t kb = (uint32_t)(ks * 32);
                        uint32_t a[2][4], b[2][4];
                        ldsm4(a[0], uAcur + aOff0 + kb);
                        ldsm4(a[1], uAcur + aOff1 + kb);
                        ldsm4(b[0], uBcur + bOff0 + kb);
                        ldsm4(b[1], uBcur + bOff1 + kb);
                        #pragma unroll
                        for (int mt = 0; mt < 2; mt++) {
                            #pragma unroll
                            for (int j = 0; j < 4; j++) {
                                mma16816h(c[mt][j], a[mt],
                                          b[j >> 1][(j & 1) * 2], b[j >> 1][(j & 1) * 2 + 1]);
                            }
                        }
                    }
                }

                // ---- Epilogue: bias, leaky, row norms (consumer-only barrier) ----
                #pragma unroll
                for (int j = 0; j < 4; j++) {
                    int col0 = n0 + j * 8 + 2 * t4;
                    float b0 = sBias[col0];
                    float b1 = sBias[col0 + 1];
                    #pragma unroll
                    for (int mt = 0; mt < 2; mt++) {
                        c[mt][j][0] += b0; c[mt][j][1] += b1;
                        c[mt][j][2] += b0; c[mt][j][3] += b1;
                    }
                }
                #pragma unroll
                for (int mt = 0; mt < 2; mt++)
                    #pragma unroll
                    for (int j = 0; j < 4; j++)
                        #pragma unroll
                        for (int q = 0; q < 4; q++) {
                            float v = c[mt][j][q];
                            c[mt][j][q] = v > 0.f ? v : 0.01f * v;
                        }

                float ss[2][2] = {{0.f, 0.f}, {0.f, 0.f}};
                #pragma unroll
                for (int mt = 0; mt < 2; mt++)
                    #pragma unroll
                    for (int j = 0; j < 4; j++) {
                        ss[mt][0] += c[mt][j][0] * c[mt][j][0] + c[mt][j][1] * c[mt][j][1];
                        ss[mt][1] += c[mt][j][2] * c[mt][j][2] + c[mt][j][3] * c[mt][j][3];
                    }
                #pragma unroll
                for (int o = 1; o <= 2; o <<= 1) {
                    #pragma unroll
                    for (int mt = 0; mt < 2; mt++) {
                        ss[mt][0] += __shfl_xor_sync(0xffffffffu, ss[mt][0], o);
                        ss[mt][1] += __shfl_xor_sync(0xffffffffu, ss[mt][1], o);
                    }
                }
                if (t4 == 0) {
                    #pragma unroll
                    for (int mt = 0; mt < 2; mt++) {
                        sPart[m0 + mt * 16 + g][wn] = ss[mt][0];
                        sPart[m0 + mt * 16 + g + 8][wn] = ss[mt][1];
                    }
                }
                asm volatile("bar.sync 1, 256;" ::: "memory");

                #pragma unroll
                for (int mt = 0; mt < 2; mt++) {
                    #pragma unroll
                    for (int h = 0; h < 2; h++) {
                        int row = m0 + mt * 16 + g + h * 8;
                        float tot = sPart[row][0] + sPart[row][1] + sPart[row][2] + sPart[row][3];
                        float scale = 1.0f / fmaxf(sqrtf(tot), 1e-12f);
                        int rg = rbase + row;
                        if (rg < NTOT) {
                            float* dst = g_final + (size_t)rg * FD + (size_t)(layer + 1) * D;
                            #pragma unroll
                            for (int j = 0; j < 4; j++) {
                                int col0 = n0 + j * 8 + 2 * t4;
                                *(float2*)(dst + col0) =
                                    make_float2(c[mt][j][h * 2] * scale, c[mt][j][h * 2 + 1] * scale);
                            }
                        }
                    }
                }
            }
            __syncthreads();
        }
    }
}

// ---------------------------------------------------------------------------
// Final dot
// ---------------------------------------------------------------------------
__global__ void k_dot(const int* __restrict__ uIdx, const int* __restrict__ iIdx,
                      float* __restrict__ out) {
    int b = blockIdx.x * (blockDim.x >> 5) + (threadIdx.x >> 5);
    if (b >= BATCH) return;
    int lane = threadIdx.x & 31;
    int u = uIdx[b];
    int it = iIdx[b] + NUM_USERS;
    const float4* pu = (const float4*)(g_final + (size_t)u * FD);
    const float4* pi = (const float4*)(g_final + (size_t)it * FD);
    float s = 0.f;
    #pragma unroll
    for (int q = 0; q < 4; q++) {
        float4 a = pu[lane + 32 * q];
        float4 c = pi[lane + 32 * q];
        s += a.x * c.x + a.y * c.y + a.z * c.z + a.w * c.w;
    }
    #pragma unroll
    for (int o = 16; o > 0; o >>= 1)
        s += __shfl_xor_sync(0xffffffffu, s, o);
    if (lane == 0) out[b] = s;
}

// ---------------------------------------------------------------------------
extern "C" void kernel_launch(void* const* d_in, const int* in_sizes, int n_in,
                              void* d_out, int out_size) {
    const int*   userIdx = (const int*)d_in[0];
    const int*   itemIdx = (const int*)d_in[1];
    const int*   rows    = (const int*)d_in[2];
    const int*   cols    = (const int*)d_in[3];
    const float* vals    = (const float*)d_in[4];
    const float* uE      = (const float*)d_in[5];
    const float* iE      = (const float*)d_in[6];
    const float* Wlin    = (const float*)d_in[7];
    const float* blin    = (const float*)d_in[8];
    const float* Wint    = (const float*)d_in[9];
    const float* bint    = (const float*)d_in[10];
    float* out = (float*)d_out;

    const int smem_fused = 2 * BTILE_B + 4 * ATILE_B;  // 139264 B -> 1 CTA/SM
    cudaFuncSetAttribute(k_fused, cudaFuncAttributeMaxDynamicSharedMemorySize, smem_fused);

    const int vec_total = NTOT * (D / 4);
    k_init<<<(vec_total + 255) / 256, 256>>>(uE, iE);   // also zeroes g_cnt
    k_wconv<<<(3 * 2 * 128 * 64 + 255) / 256, 256>>>(Wlin, Wint);

    // CSR build (once per launch)
    k_count<<<(NNZ + 255) / 256, 256>>>(rows);
    k_scan1<<<SCAN_NB, 256>>>();
    k_scan2<<<1, 128>>>();
    k_scan3<<<(NTOT + 255) / 256, 256>>>();
    k_scatter<<<(NNZ + 255) / 256, 256>>>(rows, cols, vals);

    for (int l = 0; l < NLAYERS; l++)
        k_fused<<<NSM, NTHR, smem_fused>>>(blin, bint, l);

    k_dot<<<(BATCH + 7) / 8, 256>>>(userIdx, itemIdx, out);
}

// round 14
// speedup vs baseline: 1.8056x; 1.8056x over previous
#include <cuda_runtime.h>
#include <cuda_fp16.h>
#include <cstdint>

#define NUM_USERS 30000
#define NUM_ITEMS 70000
#define NTOT      100000
#define D         128
#define NNZ       1000000
#define NLAYERS   3
#define BATCH     16384
#define FD        512   // D * (1 + NLAYERS)

#define SCAN_BS   1024
#define SCAN_NB   ((NTOT + SCAN_BS - 1) / SCAN_BS)  // 98

// Scratch (no cudaMalloc allowed)
__device__ float  g_final[(size_t)NTOT * FD];
__device__ float  g_Lx[(size_t)NTOT * D];
__device__ int    g_cnt[NTOT];
__device__ int    g_start[NTOT + 1];
__device__ int    g_cursor[NTOT];
__device__ int    g_ecol[NNZ];
__device__ float  g_eval[NNZ];
__device__ int    g_bsum[SCAN_NB];
__device__ int    g_boff[SCAN_NB];
// Pre-transposed fp16 weight images: per (layer, phase{lin,int}): B[n][k]=W[k][n], 8192 u32 (32KB)
__device__ uint32_t g_wimg[3 * 2 * 8192];

// ======================= mma.sync helpers =======================
__device__ __forceinline__ uint32_t smem_u32(const void* p) {
    uint32_t a;
    asm("{ .reg .u64 t; cvta.to.shared.u64 t, %1; cvt.u32.u64 %0, t; }" : "=r"(a) : "l"(p));
    return a;
}
__device__ __forceinline__ void ldsm4(uint32_t* r, uint32_t addr) {
    asm volatile("ldmatrix.sync.aligned.m8n8.x4.shared.b16 {%0,%1,%2,%3}, [%4];"
                 : "=r"(r[0]), "=r"(r[1]), "=r"(r[2]), "=r"(r[3]) : "r"(addr));
}
__device__ __forceinline__ void mma16816h(float* d, const uint32_t* a, uint32_t b0, uint32_t b1) {
    asm volatile(
        "mma.sync.aligned.m16n8k16.row.col.f32.f16.f16.f32 "
        "{%0,%1,%2,%3}, {%4,%5,%6,%7}, {%8,%9}, {%0,%1,%2,%3};"
        : "+f"(d[0]), "+f"(d[1]), "+f"(d[2]), "+f"(d[3])
        : "r"(a[0]), "r"(a[1]), "r"(a[2]), "r"(a[3]), "r"(b0), "r"(b1));
}

#define TPITCH_B 272
#define MTILE    64
#define ATILE_B  (MTILE * TPITCH_B)   // 17408
#define BTILE_B  (128 * TPITCH_B)     // 34816
#define NTHR     256
#define NSM      148
#define NTILES   ((NTOT + MTILE - 1) / MTILE)   // 1563

// ---------------------------------------------------------------------------
// Init: features slice 0 + zero g_cnt (fused)
// ---------------------------------------------------------------------------
__global__ void k_init(const float* __restrict__ uE, const float* __restrict__ iE) {
    int idx = blockIdx.x * blockDim.x + threadIdx.x;
    const int total = NTOT * (D / 4);
    if (idx < total) {
        int r = idx >> 5;
        int q = idx & 31;
        float4 v = (r < NUM_USERS)
            ? ((const float4*)uE)[(size_t)r * (D / 4) + q]
            : ((const float4*)iE)[(size_t)(r - NUM_USERS) * (D / 4) + q];
        ((float4*)g_final)[(size_t)r * (FD / 4) + q] = v;
    }
    if (idx < NTOT) g_cnt[idx] = 0;
}

// ---------------------------------------------------------------------------
// Weight transpose+fp16 precompute (once). B[n][k] = W[k][n].
// ---------------------------------------------------------------------------
__global__ void k_wconv(const float* __restrict__ Wlin, const float* __restrict__ Wint) {
    int idx = blockIdx.x * blockDim.x + threadIdx.x;
    const int total = 3 * 2 * 128 * 64;
    if (idx >= total) return;
    int k2 = idx & 63;
    int n  = (idx >> 6) & 127;
    int lp = idx >> 13;
    int p  = lp & 1;
    int l  = lp >> 1;
    int k  = k2 * 2;
    const float* W = (p ? Wint : Wlin) + (size_t)l * D * D;
    __half2 h = __floats2half2_rn(W[(size_t)k * 128 + n], W[(size_t)(k + 1) * 128 + n]);
    g_wimg[(size_t)(l * 2 + p) * 8192 + n * 64 + k2] = *(uint32_t*)&h;
}

// ---------------------------------------------------------------------------
// CSR build
// ---------------------------------------------------------------------------
__global__ void k_count(const int* __restrict__ rows) {
    int e = blockIdx.x * blockDim.x + threadIdx.x;
    if (e < NNZ) atomicAdd(&g_cnt[rows[e]], 1);
}
__global__ void k_scan1() {
    __shared__ int wsum[8];
    int t = threadIdx.x;
    int base = blockIdx.x * SCAN_BS + t * 4;
    int c0 = 0, c1 = 0, c2 = 0, c3 = 0;
    if (base + 3 < NTOT) {
        int4 c = *(const int4*)(g_cnt + base);
        c0 = c.x; c1 = c.y; c2 = c.z; c3 = c.w;
    } else {
        if (base + 0 < NTOT) c0 = g_cnt[base + 0];
        if (base + 1 < NTOT) c1 = g_cnt[base + 1];
        if (base + 2 < NTOT) c2 = g_cnt[base + 2];
        if (base + 3 < NTOT) c3 = g_cnt[base + 3];
    }
    int tot = c0 + c1 + c2 + c3;
    int inc = tot;
    #pragma unroll
    for (int d = 1; d < 32; d <<= 1) {
        int v = __shfl_up_sync(0xffffffffu, inc, d);
        if ((t & 31) >= d) inc += v;
    }
    if ((t & 31) == 31) wsum[t >> 5] = inc;
    __syncthreads();
    if (t < 8) {
        int v = wsum[t];
        int wi = v;
        #pragma unroll
        for (int d = 1; d < 8; d <<= 1) {
            int u = __shfl_up_sync(0xffu, wi, d);
            if (t >= d) wi += u;
        }
        wsum[t] = wi - v;
        if (t == 7) g_bsum[blockIdx.x] = wi;
    }
    __syncthreads();
    int off = wsum[t >> 5] + (inc - tot);
    if (base + 0 < NTOT) g_start[base + 0] = off;
    if (base + 1 < NTOT) g_start[base + 1] = off + c0;
    if (base + 2 < NTOT) g_start[base + 2] = off + c0 + c1;
    if (base + 3 < NTOT) g_start[base + 3] = off + c0 + c1 + c2;
}
__global__ void k_scan2() {
    __shared__ int wsum[4];
    int t = threadIdx.x;
    int v = (t < SCAN_NB) ? g_bsum[t] : 0;
    int inc = v;
    #pragma unroll
    for (int d = 1; d < 32; d <<= 1) {
        int u = __shfl_up_sync(0xffffffffu, inc, d);
        if ((t & 31) >= d) inc += u;
    }
    if ((t & 31) == 31) wsum[t >> 5] = inc;
    __syncthreads();
    if (t < 4) {
        int w = wsum[t];
        int wi = w;
        #pragma unroll
        for (int d = 1; d < 4; d <<= 1) {
            int u = __shfl_up_sync(0xfu, wi, d);
            if (t >= d) wi += u;
        }
        wsum[t] = wi - w;
    }
    __syncthreads();
    if (t < SCAN_NB) g_boff[t] = wsum[t >> 5] + (inc - v);
    if (t == 0) g_start[NTOT] = NNZ;
}
__global__ void k_scan3() {
    int i = blockIdx.x * blockDim.x + threadIdx.x;
    if (i >= NTOT) return;
    int s = g_start[i] + g_boff[i / SCAN_BS];
    g_start[i] = s;
    g_cursor[i] = s;
}
__global__ void k_scatter(const int* __restrict__ rows, const int* __restrict__ cols,
                          const float* __restrict__ vals) {
    int e = blockIdx.x * blockDim.x + threadIdx.x;
    if (e >= NNZ) return;
    int p = atomicAdd(&g_cursor[rows[e]], 1);
    g_ecol[p] = cols[e];
    g_eval[p] = vals[e];
}

// ---------------------------------------------------------------------------
// SpMM gather (proven fp32 version)
// ---------------------------------------------------------------------------
__global__ void k_spmm_csr(int layer) {
    int r = blockIdx.x * (blockDim.x >> 5) + (threadIdx.x >> 5);
    if (r >= NTOT) return;
    int lane = threadIdx.x & 31;
    int s = g_start[r];
    int e = g_start[r + 1];
    const float* fb = g_final + (size_t)layer * D;
    float4 acc = make_float4(0.f, 0.f, 0.f, 0.f);
    for (int base = s; base < e; base += 32) {
        int idx = base + lane;
        int c = 0; float v = 0.f;
        if (idx < e) { c = g_ecol[idx]; v = g_eval[idx]; }
        int cnt = min(32, e - base);
        int j = 0;
        for (; j + 4 <= cnt; j += 4) {
            int   c0 = __shfl_sync(0xffffffffu, c, j + 0);
            int   c1 = __shfl_sync(0xffffffffu, c, j + 1);
            int   c2 = __shfl_sync(0xffffffffu, c, j + 2);
            int   c3 = __shfl_sync(0xffffffffu, c, j + 3);
            float v0 = __shfl_sync(0xffffffffu, v, j + 0);
            float v1 = __shfl_sync(0xffffffffu, v, j + 1);
            float v2 = __shfl_sync(0xffffffffu, v, j + 2);
            float v3 = __shfl_sync(0xffffffffu, v, j + 3);
            float4 x0 = ((const float4*)(fb + (size_t)c0 * FD))[lane];
            float4 x1 = ((const float4*)(fb + (size_t)c1 * FD))[lane];
            float4 x2 = ((const float4*)(fb + (size_t)c2 * FD))[lane];
            float4 x3 = ((const float4*)(fb + (size_t)c3 * FD))[lane];
            acc.x += v0 * x0.x + v1 * x1.x + v2 * x2.x + v3 * x3.x;
            acc.y += v0 * x0.y + v1 * x1.y + v2 * x2.y + v3 * x3.y;
            acc.z += v0 * x0.z + v1 * x1.z + v2 * x2.z + v3 * x3.z;
            acc.w += v0 * x0.w + v1 * x1.w + v2 * x2.w + v3 * x3.w;
        }
        for (; j < cnt; j++) {
            int   cj = __shfl_sync(0xffffffffu, c, j);
            float vj = __shfl_sync(0xffffffffu, v, j);
            float4 x = ((const float4*)(fb + (size_t)cj * FD))[lane];
            acc.x += vj * x.x; acc.y += vj * x.y;
            acc.z += vj * x.z; acc.w += vj * x.w;
        }
    }
    ((float4*)(g_Lx + (size_t)r * D))[lane] = acc;
}

// ---------------------------------------------------------------------------
// Persistent tensor-core dual-GEMM (R12 base), single-sync pipeline:
//   per tile: LDG prefetch(t+1) -> mainloop(t) -> convert_sts(t+1 -> buf^1)
//   -> epilogue compute -> sPart[i&1] store -> ONE __syncthreads ->
//   norm read + STG (no trailing barrier; sPart double-buffered).
// B images resident in smem for the whole kernel.
// smem: 2x34KB B + 4x17KB A (double-buffered S/P) = 136KB -> 1 CTA/SM.
// ---------------------------------------------------------------------------
__global__ void __launch_bounds__(NTHR) k_gemm_mma(const float* __restrict__ blin,
                                                   const float* __restrict__ bint,
                                                   int layer) {
    extern __shared__ char dsm[];
    __shared__ float sPart[2][MTILE][4];
    __shared__ float sBias[128];

    char* sBlin = dsm;
    char* sBint = dsm + BTILE_B;
    char* sA    = dsm + 2 * BTILE_B;
    uint32_t uBase = smem_u32(dsm);
    uint32_t uBlin = uBase;
    uint32_t uBint = uBase + BTILE_B;
    uint32_t uA    = uBase + 2 * BTILE_B;

    int tid = threadIdx.x;
    int wid = tid >> 5;
    int lane = tid & 31;
    int wm = wid & 1, wn = wid >> 1;
    int m0 = wm * 32, n0 = wn * 32;
    int g = lane >> 2, t4 = lane & 3;

    // ---- Prologue: B images + bias (once per CTA) ----
    {
        const uint32_t* srcL = g_wimg + (size_t)(layer * 2 + 0) * 8192;
        const uint32_t* srcI = g_wimg + (size_t)(layer * 2 + 1) * 8192;
        for (int i = tid; i < 2048; i += NTHR) {
            int n = i >> 4;
            int jj = i & 15;
            *(uint4*)(sBlin + n * TPITCH_B + jj * 16) = ((const uint4*)(srcL + n * 64))[jj];
            *(uint4*)(sBint + n * TPITCH_B + jj * 16) = ((const uint4*)(srcI + n * 64))[jj];
        }
        if (tid < 128)
            sBias[tid] = __ldg(blin + (size_t)layer * D + tid) + __ldg(bint + (size_t)layer * D + tid);
    }

    int aRow = m0 + (lane & 15);
    uint32_t aOff0 = (uint32_t)(aRow * TPITCH_B + (lane >> 4) * 16);
    uint32_t aOff1 = aOff0 + 16 * TPITCH_B;
    int bRow = n0 + ((lane >> 4) << 3) + (lane & 7);
    uint32_t bOff0 = (uint32_t)(bRow * TPITCH_B + ((lane >> 3) & 1) * 16);
    uint32_t bOff1 = bOff0 + 16 * TPITCH_B;

    float4 rl[8], rf[8];

    auto load_regs = [&](int rbase) {
        #pragma unroll
        for (int i = 0; i < 4; i++) {
            int gg = tid + i * NTHR;
            int m = gg >> 4;
            int kg = (gg & 15) << 3;
            int r = rbase + m;
            if (r < NTOT) {
                const float4* lp4 = (const float4*)(g_Lx + (size_t)r * D + kg);
                const float4* fp4 = (const float4*)(g_final + (size_t)r * FD + (size_t)layer * D + kg);
                rl[2 * i + 0] = lp4[0]; rl[2 * i + 1] = lp4[1];
                rf[2 * i + 0] = fp4[0]; rf[2 * i + 1] = fp4[1];
            } else {
                float4 z = make_float4(0.f, 0.f, 0.f, 0.f);
                rl[2 * i] = z; rl[2 * i + 1] = z;
                rf[2 * i] = z; rf[2 * i + 1] = z;
            }
        }
    };
    auto convert_sts = [&](int buf) {
        char* sS = sA + buf * 2 * ATILE_B;
        char* sP = sS + ATILE_B;
        #pragma unroll
        for (int i = 0; i < 4; i++) {
            int gg = tid + i * NTHR;
            int m = gg >> 4;
            int kg = (gg & 15) << 3;
            float4 l0 = rl[2 * i], l1 = rl[2 * i + 1];
            float4 f0 = rf[2 * i], f1 = rf[2 * i + 1];
            uint32_t sv[4], pv[4];
            __half2 h;
            h = __floats2half2_rn(l0.x + f0.x, l0.y + f0.y); sv[0] = *(uint32_t*)&h;
            h = __floats2half2_rn(l0.z + f0.z, l0.w + f0.w); sv[1] = *(uint32_t*)&h;
            h = __floats2half2_rn(l1.x + f1.x, l1.y + f1.y); sv[2] = *(uint32_t*)&h;
            h = __floats2half2_rn(l1.z + f1.z, l1.w + f1.w); sv[3] = *(uint32_t*)&h;
            h = __floats2half2_rn(l0.x * f0.x, l0.y * f0.y); pv[0] = *(uint32_t*)&h;
            h = __floats2half2_rn(l0.z * f0.z, l0.w * f0.w); pv[1] = *(uint32_t*)&h;
            h = __floats2half2_rn(l1.x * f1.x, l1.y * f1.y); pv[2] = *(uint32_t*)&h;
            h = __floats2half2_rn(l1.z * f1.z, l1.w * f1.w); pv[3] = *(uint32_t*)&h;
            int off = m * TPITCH_B + kg * 2;
            *(uint4*)(sS + off) = make_uint4(sv[0], sv[1], sv[2], sv[3]);
            *(uint4*)(sP + off) = make_uint4(pv[0], pv[1], pv[2], pv[3]);
        }
    };

    // Prologue fill: tile blockIdx.x -> buffer 0
    load_regs(blockIdx.x * MTILE);
    convert_sts(0);
    __syncthreads();

    int buf = 0;
    int it = 0;
    for (int t = blockIdx.x; t * MTILE < NTOT; t += NSM, it++) {
        int tn = t + NSM;
        bool have_next = (tn * MTILE < NTOT);
        if (have_next) load_regs(tn * MTILE);   // LDGs in flight during mainloop

        float c[2][4][4];
        #pragma unroll
        for (int mt = 0; mt < 2; mt++)
            #pragma unroll
            for (int j = 0; j < 4; j++)
                #pragma unroll
                for (int q = 0; q < 4; q++) c[mt][j][q] = 0.f;

        // ---- Mainloop: both phases, B resident ----
        uint32_t uS = uA + buf * 2 * ATILE_B;
        #pragma unroll
        for (int phase = 0; phase < 2; phase++) {
            uint32_t uAcur = uS + phase * ATILE_B;
            uint32_t uBcur = phase ? uBint : uBlin;
            #pragma unroll
            for (int ks = 0; ks < 8; ks++) {
                uint32_t kb = (uint32_t)(ks * 32);
                uint32_t a[2][4], b[2][4];
                ldsm4(a[0], uAcur + aOff0 + kb);
                ldsm4(a[1], uAcur + aOff1 + kb);
                ldsm4(b[0], uBcur + bOff0 + kb);
                ldsm4(b[1], uBcur + bOff1 + kb);
                #pragma unroll
                for (int mt = 0; mt < 2; mt++) {
                    #pragma unroll
                    for (int j = 0; j < 4; j++) {
                        mma16816h(c[mt][j], a[mt],
                                  b[j >> 1][(j & 1) * 2], b[j >> 1][(j & 1) * 2 + 1]);
                    }
                }
            }
        }

        // ---- Convert next tile into alternate buffer (before epilogue) ----
        if (have_next) convert_sts(buf ^ 1);

        // ---- Epilogue compute: bias, leaky, partial row norms ----
        int rbase = t * MTILE;
        #pragma unroll
        for (int j = 0; j < 4; j++) {
            int col0 = n0 + j * 8 + 2 * t4;
            float b0 = sBias[col0];
            float b1 = sBias[col0 + 1];
            #pragma unroll
            for (int mt = 0; mt < 2; mt++) {
                c[mt][j][0] += b0; c[mt][j][1] += b1;
                c[mt][j][2] += b0; c[mt][j][3] += b1;
            }
        }
        #pragma unroll
        for (int mt = 0; mt < 2; mt++)
            #pragma unroll
            for (int j = 0; j < 4; j++)
                #pragma unroll
                for (int q = 0; q < 4; q++) {
                    float v = c[mt][j][q];
                    c[mt][j][q] = v > 0.f ? v : 0.01f * v;
                }

        float ss[2][2] = {{0.f, 0.f}, {0.f, 0.f}};
        #pragma unroll
        for (int mt = 0; mt < 2; mt++)
            #pragma unroll
            for (int j = 0; j < 4; j++) {
                ss[mt][0] += c[mt][j][0] * c[mt][j][0] + c[mt][j][1] * c[mt][j][1];
                ss[mt][1] += c[mt][j][2] * c[mt][j][2] + c[mt][j][3] * c[mt][j][3];
            }
        #pragma unroll
        for (int o = 1; o <= 2; o <<= 1) {
            #pragma unroll
            for (int mt = 0; mt < 2; mt++) {
                ss[mt][0] += __shfl_xor_sync(0xffffffffu, ss[mt][0], o);
                ss[mt][1] += __shfl_xor_sync(0xffffffffu, ss[mt][1], o);
            }
        }
        int pb = it & 1;
        if (t4 == 0) {
            #pragma unroll
            for (int mt = 0; mt < 2; mt++) {
                sPart[pb][m0 + mt * 16 + g][wn] = ss[mt][0];
                sPart[pb][m0 + mt * 16 + g + 8][wn] = ss[mt][1];
            }
        }

        // ---- Single barrier: covers convert STS + sPart exchange ----
        __syncthreads();

        #pragma unroll
        for (int mt = 0; mt < 2; mt++) {
            #pragma unroll
            for (int h = 0; h < 2; h++) {
                int row = m0 + mt * 16 + g + h * 8;
                float tot = sPart[pb][row][0] + sPart[pb][row][1]
                          + sPart[pb][row][2] + sPart[pb][row][3];
                float scale = 1.0f / fmaxf(sqrtf(tot), 1e-12f);
                int rg = rbase + row;
                if (rg < NTOT) {
                    float* dst = g_final + (size_t)rg * FD + (size_t)(layer + 1) * D;
                    #pragma unroll
                    for (int j = 0; j < 4; j++) {
                        int col0 = n0 + j * 8 + 2 * t4;
                        *(float2*)(dst + col0) =
                            make_float2(c[mt][j][h * 2] * scale, c[mt][j][h * 2 + 1] * scale);
                    }
                }
            }
        }
        buf ^= 1;
    }
}

// ---------------------------------------------------------------------------
// Final dot
// ---------------------------------------------------------------------------
__global__ void k_dot(const int* __restrict__ uIdx, const int* __restrict__ iIdx,
                      float* __restrict__ out) {
    int b = blockIdx.x * (blockDim.x >> 5) + (threadIdx.x >> 5);
    if (b >= BATCH) return;
    int lane = threadIdx.x & 31;
    int u = uIdx[b];
    int it = iIdx[b] + NUM_USERS;
    const float4* pu = (const float4*)(g_final + (size_t)u * FD);
    const float4* pi = (const float4*)(g_final + (size_t)it * FD);
    float s = 0.f;
    #pragma unroll
    for (int q = 0; q < 4; q++) {
        float4 a = pu[lane + 32 * q];
        float4 c = pi[lane + 32 * q];
        s += a.x * c.x + a.y * c.y + a.z * c.z + a.w * c.w;
    }
    #pragma unroll
    for (int o = 16; o > 0; o >>= 1)
        s += __shfl_xor_sync(0xffffffffu, s, o);
    if (lane == 0) out[b] = s;
}

// ---------------------------------------------------------------------------
extern "C" void kernel_launch(void* const* d_in, const int* in_sizes, int n_in,
                              void* d_out, int out_size) {
    const int*   userIdx = (const int*)d_in[0];
    const int*   itemIdx = (const int*)d_in[1];
    const int*   rows    = (const int*)d_in[2];
    const int*   cols    = (const int*)d_in[3];
    const float* vals    = (const float*)d_in[4];
    const float* uE      = (const float*)d_in[5];
    const float* iE      = (const float*)d_in[6];
    const float* Wlin    = (const float*)d_in[7];
    const float* blin    = (const float*)d_in[8];
    const float* Wint    = (const float*)d_in[9];
    const float* bint    = (const float*)d_in[10];
    float* out = (float*)d_out;

    const int smem_mma = 2 * BTILE_B + 4 * ATILE_B;  // 139264 B -> 1 CTA/SM
    cudaFuncSetAttribute(k_gemm_mma, cudaFuncAttributeMaxDynamicSharedMemorySize, smem_mma);

    const int vec_total = NTOT * (D / 4);
    k_init<<<(vec_total + 255) / 256, 256>>>(uE, iE);   // also zeroes g_cnt
    k_wconv<<<(3 * 2 * 128 * 64 + 255) / 256, 256>>>(Wlin, Wint);

    // CSR build (once per launch)
    k_count<<<(NNZ + 255) / 256, 256>>>(rows);
    k_scan1<<<SCAN_NB, 256>>>();
    k_scan2<<<1, 128>>>();
    k_scan3<<<(NTOT + 255) / 256, 256>>>();
    k_scatter<<<(NNZ + 255) / 256, 256>>>(rows, cols, vals);

    for (int l = 0; l < NLAYERS; l++) {
        k_spmm_csr<<<(NTOT + 7) / 8, 256>>>(l);
        k_gemm_mma<<<NSM, NTHR, smem_mma>>>(blin, bint, l);
    }

    k_dot<<<(BATCH + 7) / 8, 256>>>(userIdx, itemIdx, out);
}

// round 15
// speedup vs baseline: 1.8234x; 1.0099x over previous
#include <cuda_runtime.h>
#include <cuda_fp16.h>
#include <cstdint>

#define NUM_USERS 30000
#define NUM_ITEMS 70000
#define NTOT      100000
#define D         128
#define NNZ       1000000
#define NLAYERS   3
#define BATCH     16384
#define FD        512   // D * (1 + NLAYERS)

#define SCAN_BS   1024
#define SCAN_NB   ((NTOT + SCAN_BS - 1) / SCAN_BS)  // 98

// Scratch (no cudaMalloc allowed)
__device__ float  g_final[(size_t)NTOT * FD];
__device__ float  g_Lx[(size_t)NTOT * D];
__device__ __half g_fh16[(size_t)NTOT * D];   // fp16 current-layer feature plane (gather source)
__device__ int    g_cnt[NTOT];
__device__ int    g_start[NTOT + 1];
__device__ int    g_cursor[NTOT];
__device__ int2   g_edge[NNZ];                // packed {col, val_bits}
__device__ int    g_bsum[SCAN_NB];
__device__ int    g_boff[SCAN_NB];
// Pre-transposed fp16 weight images: per (layer, phase{lin,int}): B[n][k]=W[k][n], 8192 u32 (32KB)
__device__ uint32_t g_wimg[3 * 2 * 8192];

// ======================= mma.sync helpers =======================
__device__ __forceinline__ uint32_t smem_u32(const void* p) {
    uint32_t a;
    asm("{ .reg .u64 t; cvta.to.shared.u64 t, %1; cvt.u32.u64 %0, t; }" : "=r"(a) : "l"(p));
    return a;
}
__device__ __forceinline__ void ldsm4(uint32_t* r, uint32_t addr) {
    asm volatile("ldmatrix.sync.aligned.m8n8.x4.shared.b16 {%0,%1,%2,%3}, [%4];"
                 : "=r"(r[0]), "=r"(r[1]), "=r"(r[2]), "=r"(r[3]) : "r"(addr));
}
__device__ __forceinline__ void mma16816h(float* d, const uint32_t* a, uint32_t b0, uint32_t b1) {
    asm volatile(
        "mma.sync.aligned.m16n8k16.row.col.f32.f16.f16.f32 "
        "{%0,%1,%2,%3}, {%4,%5,%6,%7}, {%8,%9}, {%0,%1,%2,%3};"
        : "+f"(d[0]), "+f"(d[1]), "+f"(d[2]), "+f"(d[3])
        : "r"(a[0]), "r"(a[1]), "r"(a[2]), "r"(a[3]), "r"(b0), "r"(b1));
}

#define TPITCH_B 272
#define MTILE    64
#define ATILE_B  (MTILE * TPITCH_B)   // 17408
#define BTILE_B  (128 * TPITCH_B)     // 34816
#define NTHR     256
#define NSM      148
#define NTILES   ((NTOT + MTILE - 1) / MTILE)   // 1563

// ---------------------------------------------------------------------------
// Init: features slice 0 (fp32 + fp16 plane) + zero g_cnt (fused)
// ---------------------------------------------------------------------------
__global__ void k_init(const float* __restrict__ uE, const float* __restrict__ iE) {
    int idx = blockIdx.x * blockDim.x + threadIdx.x;
    const int total = NTOT * (D / 4);
    if (idx < total) {
        int r = idx >> 5;
        int q = idx & 31;
        float4 v = (r < NUM_USERS)
            ? ((const float4*)uE)[(size_t)r * (D / 4) + q]
            : ((const float4*)iE)[(size_t)(r - NUM_USERS) * (D / 4) + q];
        ((float4*)g_final)[(size_t)r * (FD / 4) + q] = v;
        __half2 h0 = __floats2half2_rn(v.x, v.y);
        __half2 h1 = __floats2half2_rn(v.z, v.w);
        ((uint2*)g_fh16)[(size_t)r * (D / 4) + q] =
            make_uint2(*(uint32_t*)&h0, *(uint32_t*)&h1);
    }
    if (idx < NTOT) g_cnt[idx] = 0;
}

// ---------------------------------------------------------------------------
// Weight transpose+fp16 precompute (once). B[n][k] = W[k][n].
// ---------------------------------------------------------------------------
__global__ void k_wconv(const float* __restrict__ Wlin, const float* __restrict__ Wint) {
    int idx = blockIdx.x * blockDim.x + threadIdx.x;
    const int total = 3 * 2 * 128 * 64;
    if (idx >= total) return;
    int k2 = idx & 63;
    int n  = (idx >> 6) & 127;
    int lp = idx >> 13;
    int p  = lp & 1;
    int l  = lp >> 1;
    int k  = k2 * 2;
    const float* W = (p ? Wint : Wlin) + (size_t)l * D * D;
    __half2 h = __floats2half2_rn(W[(size_t)k * 128 + n], W[(size_t)(k + 1) * 128 + n]);
    g_wimg[(size_t)(l * 2 + p) * 8192 + n * 64 + k2] = *(uint32_t*)&h;
}

// ---------------------------------------------------------------------------
// CSR build
// ---------------------------------------------------------------------------
__global__ void k_count(const int* __restrict__ rows) {
    int e = blockIdx.x * blockDim.x + threadIdx.x;
    if (e < NNZ) atomicAdd(&g_cnt[rows[e]], 1);
}
__global__ void k_scan1() {
    __shared__ int wsum[8];
    int t = threadIdx.x;
    int base = blockIdx.x * SCAN_BS + t * 4;
    int c0 = 0, c1 = 0, c2 = 0, c3 = 0;
    if (base + 3 < NTOT) {
        int4 c = *(const int4*)(g_cnt + base);
        c0 = c.x; c1 = c.y; c2 = c.z; c3 = c.w;
    } else {
        if (base + 0 < NTOT) c0 = g_cnt[base + 0];
        if (base + 1 < NTOT) c1 = g_cnt[base + 1];
        if (base + 2 < NTOT) c2 = g_cnt[base + 2];
        if (base + 3 < NTOT) c3 = g_cnt[base + 3];
    }
    int tot = c0 + c1 + c2 + c3;
    int inc = tot;
    #pragma unroll
    for (int d = 1; d < 32; d <<= 1) {
        int v = __shfl_up_sync(0xffffffffu, inc, d);
        if ((t & 31) >= d) inc += v;
    }
    if ((t & 31) == 31) wsum[t >> 5] = inc;
    __syncthreads();
    if (t < 8) {
        int v = wsum[t];
        int wi = v;
        #pragma unroll
        for (int d = 1; d < 8; d <<= 1) {
            int u = __shfl_up_sync(0xffu, wi, d);
            if (t >= d) wi += u;
        }
        wsum[t] = wi - v;
        if (t == 7) g_bsum[blockIdx.x] = wi;
    }
    __syncthreads();
    int off = wsum[t >> 5] + (inc - tot);
    if (base + 0 < NTOT) g_start[base + 0] = off;
    if (base + 1 < NTOT) g_start[base + 1] = off + c0;
    if (base + 2 < NTOT) g_start[base + 2] = off + c0 + c1;
    if (base + 3 < NTOT) g_start[base + 3] = off + c0 + c1 + c2;
}
__global__ void k_scan2() {
    __shared__ int wsum[4];
    int t = threadIdx.x;
    int v = (t < SCAN_NB) ? g_bsum[t] : 0;
    int inc = v;
    #pragma unroll
    for (int d = 1; d < 32; d <<= 1) {
        int u = __shfl_up_sync(0xffffffffu, inc, d);
        if ((t & 31) >= d) inc += u;
    }
    if ((t & 31) == 31) wsum[t >> 5] = inc;
    __syncthreads();
    if (t < 4) {
        int w = wsum[t];
        int wi = w;
        #pragma unroll
        for (int d = 1; d < 4; d <<= 1) {
            int u = __shfl_up_sync(0xfu, wi, d);
            if (t >= d) wi += u;
        }
        wsum[t] = wi - w;
    }
    __syncthreads();
    if (t < SCAN_NB) g_boff[t] = wsum[t >> 5] + (inc - v);
    if (t == 0) g_start[NTOT] = NNZ;
}
__global__ void k_scan3() {
    int i = blockIdx.x * blockDim.x + threadIdx.x;
    if (i >= NTOT) return;
    int s = g_start[i] + g_boff[i / SCAN_BS];
    g_start[i] = s;
    g_cursor[i] = s;
}
__global__ void k_scatter(const int* __restrict__ rows, const int* __restrict__ cols,
                          const float* __restrict__ vals) {
    int e = blockIdx.x * blockDim.x + threadIdx.x;
    if (e >= NNZ) return;
    int p = atomicAdd(&g_cursor[rows[e]], 1);
    g_edge[p] = make_int2(cols[e], __float_as_int(vals[e]));
}

// ---------------------------------------------------------------------------
// SpMM gather from fp16 plane (8B/lane), packed edges, 4-edge unroll.
// fp32 accumulate -> g_Lx fp32.
// ---------------------------------------------------------------------------
__global__ void k_spmm_csr() {
    int r = blockIdx.x * (blockDim.x >> 5) + (threadIdx.x >> 5);
    if (r >= NTOT) return;
    int lane = threadIdx.x & 31;
    int s = g_start[r];
    int e = g_start[r + 1];
    float4 acc = make_float4(0.f, 0.f, 0.f, 0.f);
    for (int base = s; base < e; base += 32) {
        int idx = base + lane;
        int c = 0; float v = 0.f;
        if (idx < e) {
            int2 ed = g_edge[idx];
            c = ed.x; v = __int_as_float(ed.y);
        }
        int cnt = min(32, e - base);
        int j = 0;
        for (; j + 4 <= cnt; j += 4) {
            int   c0 = __shfl_sync(0xffffffffu, c, j + 0);
            int   c1 = __shfl_sync(0xffffffffu, c, j + 1);
            int   c2 = __shfl_sync(0xffffffffu, c, j + 2);
            int   c3 = __shfl_sync(0xffffffffu, c, j + 3);
            float v0 = __shfl_sync(0xffffffffu, v, j + 0);
            float v1 = __shfl_sync(0xffffffffu, v, j + 1);
            float v2 = __shfl_sync(0xffffffffu, v, j + 2);
            float v3 = __shfl_sync(0xffffffffu, v, j + 3);
            uint2 x0 = ((const uint2*)(g_fh16 + (size_t)c0 * D))[lane];
            uint2 x1 = ((const uint2*)(g_fh16 + (size_t)c1 * D))[lane];
            uint2 x2 = ((const uint2*)(g_fh16 + (size_t)c2 * D))[lane];
            uint2 x3 = ((const uint2*)(g_fh16 + (size_t)c3 * D))[lane];
            float2 a0 = __half22float2(*(__half2*)&x0.x), b0 = __half22float2(*(__half2*)&x0.y);
            float2 a1 = __half22float2(*(__half2*)&x1.x), b1 = __half22float2(*(__half2*)&x1.y);
            float2 a2 = __half22float2(*(__half2*)&x2.x), b2 = __half22float2(*(__half2*)&x2.y);
            float2 a3 = __half22float2(*(__half2*)&x3.x), b3 = __half22float2(*(__half2*)&x3.y);
            acc.x += v0 * a0.x + v1 * a1.x + v2 * a2.x + v3 * a3.x;
            acc.y += v0 * a0.y + v1 * a1.y + v2 * a2.y + v3 * a3.y;
            acc.z += v0 * b0.x + v1 * b1.x + v2 * b2.x + v3 * b3.x;
            acc.w += v0 * b0.y + v1 * b1.y + v2 * b2.y + v3 * b3.y;
        }
        for (; j < cnt; j++) {
            int   cj = __shfl_sync(0xffffffffu, c, j);
            float vj = __shfl_sync(0xffffffffu, v, j);
            uint2 x = ((const uint2*)(g_fh16 + (size_t)cj * D))[lane];
            float2 a = __half22float2(*(__half2*)&x.x);
            float2 b = __half22float2(*(__half2*)&x.y);
            acc.x += vj * a.x; acc.y += vj * a.y;
            acc.z += vj * b.x; acc.w += vj * b.y;
        }
    }
    ((float4*)(g_Lx + (size_t)r * D))[lane] = acc;
}

// ---------------------------------------------------------------------------
// Persistent tensor-core dual-GEMM (R12 structure). B images resident.
// Epilogue additionally refreshes the fp16 gather plane.
// smem: 2x34KB B + 4x17KB A (double-buffered S/P) = 136KB -> 1 CTA/SM.
// ---------------------------------------------------------------------------
__global__ void __launch_bounds__(NTHR) k_gemm_mma(const float* __restrict__ blin,
                                                   const float* __restrict__ bint,
                                                   int layer) {
    extern __shared__ char dsm[];
    __shared__ float sPart[MTILE][4];
    __shared__ float sBias[128];

    char* sBlin = dsm;
    char* sBint = dsm + BTILE_B;
    char* sA    = dsm + 2 * BTILE_B;
    uint32_t uBase = smem_u32(dsm);
    uint32_t uBlin = uBase;
    uint32_t uBint = uBase + BTILE_B;
    uint32_t uA    = uBase + 2 * BTILE_B;

    int tid = threadIdx.x;
    int wid = tid >> 5;
    int lane = tid & 31;
    int wm = wid & 1, wn = wid >> 1;
    int m0 = wm * 32, n0 = wn * 32;
    int g = lane >> 2, t4 = lane & 3;

    {
        const uint32_t* srcL = g_wimg + (size_t)(layer * 2 + 0) * 8192;
        const uint32_t* srcI = g_wimg + (size_t)(layer * 2 + 1) * 8192;
        for (int i = tid; i < 2048; i += NTHR) {
            int n = i >> 4;
            int jj = i & 15;
            *(uint4*)(sBlin + n * TPITCH_B + jj * 16) = ((const uint4*)(srcL + n * 64))[jj];
            *(uint4*)(sBint + n * TPITCH_B + jj * 16) = ((const uint4*)(srcI + n * 64))[jj];
        }
        if (tid < 128)
            sBias[tid] = __ldg(blin + (size_t)layer * D + tid) + __ldg(bint + (size_t)layer * D + tid);
    }

    int aRow = m0 + (lane & 15);
    uint32_t aOff0 = (uint32_t)(aRow * TPITCH_B + (lane >> 4) * 16);
    uint32_t aOff1 = aOff0 + 16 * TPITCH_B;
    int bRow = n0 + ((lane >> 4) << 3) + (lane & 7);
    uint32_t bOff0 = (uint32_t)(bRow * TPITCH_B + ((lane >> 3) & 1) * 16);
    uint32_t bOff1 = bOff0 + 16 * TPITCH_B;

    float4 rl[8], rf[8];

    auto load_regs = [&](int rbase) {
        #pragma unroll
        for (int i = 0; i < 4; i++) {
            int gg = tid + i * NTHR;
            int m = gg >> 4;
            int kg = (gg & 15) << 3;
            int r = rbase + m;
            if (r < NTOT) {
                const float4* lp4 = (const float4*)(g_Lx + (size_t)r * D + kg);
                const float4* fp4 = (const float4*)(g_final + (size_t)r * FD + (size_t)layer * D + kg);
                rl[2 * i + 0] = lp4[0]; rl[2 * i + 1] = lp4[1];
                rf[2 * i + 0] = fp4[0]; rf[2 * i + 1] = fp4[1];
            } else {
                float4 z = make_float4(0.f, 0.f, 0.f, 0.f);
                rl[2 * i] = z; rl[2 * i + 1] = z;
                rf[2 * i] = z; rf[2 * i + 1] = z;
            }
        }
    };
    auto convert_sts = [&](int buf) {
        char* sS = sA + buf * 2 * ATILE_B;
        char* sP = sS + ATILE_B;
        #pragma unroll
        for (int i = 0; i < 4; i++) {
            int gg = tid + i * NTHR;
            int m = gg >> 4;
            int kg = (gg & 15) << 3;
            float4 l0 = rl[2 * i], l1 = rl[2 * i + 1];
            float4 f0 = rf[2 * i], f1 = rf[2 * i + 1];
            uint32_t sv[4], pv[4];
            __half2 h;
            h = __floats2half2_rn(l0.x + f0.x, l0.y + f0.y); sv[0] = *(uint32_t*)&h;
            h = __floats2half2_rn(l0.z + f0.z, l0.w + f0.w); sv[1] = *(uint32_t*)&h;
            h = __floats2half2_rn(l1.x + f1.x, l1.y + f1.y); sv[2] = *(uint32_t*)&h;
            h = __floats2half2_rn(l1.z + f1.z, l1.w + f1.w); sv[3] = *(uint32_t*)&h;
            h = __floats2half2_rn(l0.x * f0.x, l0.y * f0.y); pv[0] = *(uint32_t*)&h;
            h = __floats2half2_rn(l0.z * f0.z, l0.w * f0.w); pv[1] = *(uint32_t*)&h;
            h = __floats2half2_rn(l1.x * f1.x, l1.y * f1.y); pv[2] = *(uint32_t*)&h;
            h = __floats2half2_rn(l1.z * f1.z, l1.w * f1.w); pv[3] = *(uint32_t*)&h;
            int off = m * TPITCH_B + kg * 2;
            *(uint4*)(sS + off) = make_uint4(sv[0], sv[1], sv[2], sv[3]);
            *(uint4*)(sP + off) = make_uint4(pv[0], pv[1], pv[2], pv[3]);
        }
    };

    load_regs(blockIdx.x * MTILE);
    convert_sts(0);
    __syncthreads();

    int buf = 0;
    for (int t = blockIdx.x; t * MTILE < NTOT; t += NSM) {
        int tn = t + NSM;
        bool have_next = (tn * MTILE < NTOT);
        if (have_next) load_regs(tn * MTILE);

        float c[2][4][4];
        #pragma unroll
        for (int mt = 0; mt < 2; mt++)
            #pragma unroll
            for (int j = 0; j < 4; j++)
                #pragma unroll
                for (int q = 0; q < 4; q++) c[mt][j][q] = 0.f;

        uint32_t uS = uA + buf * 2 * ATILE_B;
        #pragma unroll
        for (int phase = 0; phase < 2; phase++) {
            uint32_t uAcur = uS + phase * ATILE_B;
            uint32_t uBcur = phase ? uBint : uBlin;
            #pragma unroll
            for (int ks = 0; ks < 8; ks++) {
                uint32_t kb = (uint32_t)(ks * 32);
                uint32_t a[2][4], b[2][4];
                ldsm4(a[0], uAcur + aOff0 + kb);
                ldsm4(a[1], uAcur + aOff1 + kb);
                ldsm4(b[0], uBcur + bOff0 + kb);
                ldsm4(b[1], uBcur + bOff1 + kb);
                #pragma unroll
                for (int mt = 0; mt < 2; mt++) {
                    #pragma unroll
                    for (int j = 0; j < 4; j++) {
                        mma16816h(c[mt][j], a[mt],
                                  b[j >> 1][(j & 1) * 2], b[j >> 1][(j & 1) * 2 + 1]);
                    }
                }
            }
        }

        // ---- Epilogue ----
        int rbase = t * MTILE;
        #pragma unroll
        for (int j = 0; j < 4; j++) {
            int col0 = n0 + j * 8 + 2 * t4;
            float b0 = sBias[col0];
            float b1 = sBias[col0 + 1];
            #pragma unroll
            for (int mt = 0; mt < 2; mt++) {
                c[mt][j][0] += b0; c[mt][j][1] += b1;
                c[mt][j][2] += b0; c[mt][j][3] += b1;
            }
        }
        #pragma unroll
        for (int mt = 0; mt < 2; mt++)
            #pragma unroll
            for (int j = 0; j < 4; j++)
                #pragma unroll
                for (int q = 0; q < 4; q++) {
                    float v = c[mt][j][q];
                    c[mt][j][q] = v > 0.f ? v : 0.01f * v;
                }

        float ss[2][2] = {{0.f, 0.f}, {0.f, 0.f}};
        #pragma unroll
        for (int mt = 0; mt < 2; mt++)
            #pragma unroll
            for (int j = 0; j < 4; j++) {
                ss[mt][0] += c[mt][j][0] * c[mt][j][0] + c[mt][j][1] * c[mt][j][1];
                ss[mt][1] += c[mt][j][2] * c[mt][j][2] + c[mt][j][3] * c[mt][j][3];
            }
        #pragma unroll
        for (int o = 1; o <= 2; o <<= 1) {
            #pragma unroll
            for (int mt = 0; mt < 2; mt++) {
                ss[mt][0] += __shfl_xor_sync(0xffffffffu, ss[mt][0], o);
                ss[mt][1] += __shfl_xor_sync(0xffffffffu, ss[mt][1], o);
            }
        }
        if (t4 == 0) {
            #pragma unroll
            for (int mt = 0; mt < 2; mt++) {
                sPart[m0 + mt * 16 + g][wn] = ss[mt][0];
                sPart[m0 + mt * 16 + g + 8][wn] = ss[mt][1];
            }
        }
        __syncthreads();

        #pragma unroll
        for (int mt = 0; mt < 2; mt++) {
            #pragma unroll
            for (int h = 0; h < 2; h++) {
                int row = m0 + mt * 16 + g + h * 8;
                float tot = sPart[row][0] + sPart[row][1] + sPart[row][2] + sPart[row][3];
                float scale = 1.0f / fmaxf(sqrtf(tot), 1e-12f);
                int rg = rbase + row;
                if (rg < NTOT) {
                    float* dst = g_final + (size_t)rg * FD + (size_t)(layer + 1) * D;
                    __half* dh = g_fh16 + (size_t)rg * D;
                    #pragma unroll
                    for (int j = 0; j < 4; j++) {
                        int col0 = n0 + j * 8 + 2 * t4;
                        float v0 = c[mt][j][h * 2] * scale;
                        float v1 = c[mt][j][h * 2 + 1] * scale;
                        *(float2*)(dst + col0) = make_float2(v0, v1);
                        __half2 hv = __floats2half2_rn(v0, v1);
                        *(uint32_t*)(dh + col0) = *(uint32_t*)&hv;
                    }
                }
            }
        }

        if (have_next) convert_sts(buf ^ 1);
        __syncthreads();
        buf ^= 1;
    }
}

// ---------------------------------------------------------------------------
// Final dot
// ---------------------------------------------------------------------------
__global__ void k_dot(const int* __restrict__ uIdx, const int* __restrict__ iIdx,
                      float* __restrict__ out) {
    int b = blockIdx.x * (blockDim.x >> 5) + (threadIdx.x >> 5);
    if (b >= BATCH) return;
    int lane = threadIdx.x & 31;
    int u = uIdx[b];
    int it = iIdx[b] + NUM_USERS;
    const float4* pu = (const float4*)(g_final + (size_t)u * FD);
    const float4* pi = (const float4*)(g_final + (size_t)it * FD);
    float s = 0.f;
    #pragma unroll
    for (int q = 0; q < 4; q++) {
        float4 a = pu[lane + 32 * q];
        float4 c = pi[lane + 32 * q];
        s += a.x * c.x + a.y * c.y + a.z * c.z + a.w * c.w;
    }
    #pragma unroll
    for (int o = 16; o > 0; o >>= 1)
        s += __shfl_xor_sync(0xffffffffu, s, o);
    if (lane == 0) out[b] = s;
}

// ---------------------------------------------------------------------------
extern "C" void kernel_launch(void* const* d_in, const int* in_sizes, int n_in,
                              void* d_out, int out_size) {
    const int*   userIdx = (const int*)d_in[0];
    const int*   itemIdx = (const int*)d_in[1];
    const int*   rows    = (const int*)d_in[2];
    const int*   cols    = (const int*)d_in[3];
    const float* vals    = (const float*)d_in[4];
    const float* uE      = (const float*)d_in[5];
    const float* iE      = (const float*)d_in[6];
    const float* Wlin    = (const float*)d_in[7];
    const float* blin    = (const float*)d_in[8];
    const float* Wint    = (const float*)d_in[9];
    const float* bint    = (const float*)d_in[10];
    float* out = (float*)d_out;

    const int smem_mma = 2 * BTILE_B + 4 * ATILE_B;  // 139264 B -> 1 CTA/SM
    cudaFuncSetAttribute(k_gemm_mma, cudaFuncAttributeMaxDynamicSharedMemorySize, smem_mma);

    const int vec_total = NTOT * (D / 4);
    k_init<<<(vec_total + 255) / 256, 256>>>(uE, iE);   // also zeroes g_cnt
    k_wconv<<<(3 * 2 * 128 * 64 + 255) / 256, 256>>>(Wlin, Wint);

    // CSR build (once per launch)
    k_count<<<(NNZ + 255) / 256, 256>>>(rows);
    k_scan1<<<SCAN_NB, 256>>>();
    k_scan2<<<1, 128>>>();
    k_scan3<<<(NTOT + 255) / 256, 256>>>();
    k_scatter<<<(NNZ + 255) / 256, 256>>>(rows, cols, vals);

    for (int l = 0; l < NLAYERS; l++) {
        k_spmm_csr<<<(NTOT + 7) / 8, 256>>>();
        k_gemm_mma<<<NSM, NTHR, smem_mma>>>(blin, bint, l);
    }

    k_dot<<<(BATCH + 7) / 8, 256>>>(userIdx, itemIdx, out);
}

// round 16
// speedup vs baseline: 1.8710x; 1.0261x over previous
#include <cuda_runtime.h>
#include <cuda_fp16.h>
#include <cstdint>

#define NUM_USERS 30000
#define NUM_ITEMS 70000
#define NTOT      100000
#define D         128
#define NNZ       1000000
#define NLAYERS   3
#define BATCH     16384
#define FD        512   // D * (1 + NLAYERS)

#define SCAN_BS   1024
#define SCAN_NB   ((NTOT + SCAN_BS - 1) / SCAN_BS)  // 98

// Scratch (no cudaMalloc allowed)
__device__ float  g_final[(size_t)NTOT * FD];
__device__ float  g_Lx[(size_t)NTOT * D];
__device__ int    g_cnt[NTOT];
__device__ int    g_start[NTOT + 1];
__device__ int    g_cursor[NTOT];
__device__ int2   g_edge[NNZ];                // packed {col, val_bits}
__device__ int    g_bsum[SCAN_NB];
__device__ int    g_boff[SCAN_NB];
// Pre-transposed fp16 weight images: per (layer, phase{lin,int}): B[n][k]=W[k][n], 8192 u32 (32KB)
__device__ uint32_t g_wimg[3 * 2 * 8192];

// ======================= mma.sync helpers =======================
__device__ __forceinline__ uint32_t smem_u32(const void* p) {
    uint32_t a;
    asm("{ .reg .u64 t; cvta.to.shared.u64 t, %1; cvt.u32.u64 %0, t; }" : "=r"(a) : "l"(p));
    return a;
}
__device__ __forceinline__ void ldsm4(uint32_t* r, uint32_t addr) {
    asm volatile("ldmatrix.sync.aligned.m8n8.x4.shared.b16 {%0,%1,%2,%3}, [%4];"
                 : "=r"(r[0]), "=r"(r[1]), "=r"(r[2]), "=r"(r[3]) : "r"(addr));
}
__device__ __forceinline__ void mma16816h(float* d, const uint32_t* a, uint32_t b0, uint32_t b1) {
    asm volatile(
        "mma.sync.aligned.m16n8k16.row.col.f32.f16.f16.f32 "
        "{%0,%1,%2,%3}, {%4,%5,%6,%7}, {%8,%9}, {%0,%1,%2,%3};"
        : "+f"(d[0]), "+f"(d[1]), "+f"(d[2]), "+f"(d[3])
        : "r"(a[0]), "r"(a[1]), "r"(a[2]), "r"(a[3]), "r"(b0), "r"(b1));
}

#define TPITCH_B 272
#define MTILE    64
#define ATILE_B  (MTILE * TPITCH_B)   // 17408
#define BTILE_B  (128 * TPITCH_B)     // 34816
#define NTHR     256
#define NSM      148
#define NTILES   ((NTOT + MTILE - 1) / MTILE)   // 1563

// ---------------------------------------------------------------------------
// Init: features slice 0 (fp32)
// ---------------------------------------------------------------------------
__global__ void k_init(const float* __restrict__ uE, const float* __restrict__ iE) {
    int idx = blockIdx.x * blockDim.x + threadIdx.x;
    const int total = NTOT * (D / 4);
    if (idx >= total) return;
    int r = idx >> 5;
    int q = idx & 31;
    float4 v = (r < NUM_USERS)
        ? ((const float4*)uE)[(size_t)r * (D / 4) + q]
        : ((const float4*)iE)[(size_t)(r - NUM_USERS) * (D / 4) + q];
    ((float4*)g_final)[(size_t)r * (FD / 4) + q] = v;
}

// ---------------------------------------------------------------------------
// Weight transpose+fp16 precompute (once). B[n][k] = W[k][n].
// ---------------------------------------------------------------------------
__global__ void k_wconv(const float* __restrict__ Wlin, const float* __restrict__ Wint) {
    int idx = blockIdx.x * blockDim.x + threadIdx.x;
    const int total = 3 * 2 * 128 * 64;
    if (idx >= total) return;
    int k2 = idx & 63;
    int n  = (idx >> 6) & 127;
    int lp = idx >> 13;
    int p  = lp & 1;
    int l  = lp >> 1;
    int k  = k2 * 2;
    const float* W = (p ? Wint : Wlin) + (size_t)l * D * D;
    __half2 h = __floats2half2_rn(W[(size_t)k * 128 + n], W[(size_t)(k + 1) * 128 + n]);
    g_wimg[(size_t)(l * 2 + p) * 8192 + n * 64 + k2] = *(uint32_t*)&h;
}

// ---------------------------------------------------------------------------
// CSR build
// ---------------------------------------------------------------------------
__global__ void k_zero_cnt() {
    int i = blockIdx.x * blockDim.x + threadIdx.x;
    if (i < NTOT) g_cnt[i] = 0;
}
__global__ void k_count(const int* __restrict__ rows) {
    int e = blockIdx.x * blockDim.x + threadIdx.x;
    if (e < NNZ) atomicAdd(&g_cnt[rows[e]], 1);
}
__global__ void k_scan1() {
    __shared__ int wsum[8];
    int t = threadIdx.x;
    int base = blockIdx.x * SCAN_BS + t * 4;
    int c0 = 0, c1 = 0, c2 = 0, c3 = 0;
    if (base + 3 < NTOT) {
        int4 c = *(const int4*)(g_cnt + base);
        c0 = c.x; c1 = c.y; c2 = c.z; c3 = c.w;
    } else {
        if (base + 0 < NTOT) c0 = g_cnt[base + 0];
        if (base + 1 < NTOT) c1 = g_cnt[base + 1];
        if (base + 2 < NTOT) c2 = g_cnt[base + 2];
        if (base + 3 < NTOT) c3 = g_cnt[base + 3];
    }
    int tot = c0 + c1 + c2 + c3;
    int inc = tot;
    #pragma unroll
    for (int d = 1; d < 32; d <<= 1) {
        int v = __shfl_up_sync(0xffffffffu, inc, d);
        if ((t & 31) >= d) inc += v;
    }
    if ((t & 31) == 31) wsum[t >> 5] = inc;
    __syncthreads();
    if (t < 8) {
        int v = wsum[t];
        int wi = v;
        #pragma unroll
        for (int d = 1; d < 8; d <<= 1) {
            int u = __shfl_up_sync(0xffu, wi, d);
            if (t >= d) wi += u;
        }
        wsum[t] = wi - v;
        if (t == 7) g_bsum[blockIdx.x] = wi;
    }
    __syncthreads();
    int off = wsum[t >> 5] + (inc - tot);
    if (base + 0 < NTOT) g_start[base + 0] = off;
    if (base + 1 < NTOT) g_start[base + 1] = off + c0;
    if (base + 2 < NTOT) g_start[base + 2] = off + c0 + c1;
    if (base + 3 < NTOT) g_start[base + 3] = off + c0 + c1 + c2;
}
__global__ void k_scan2() {
    __shared__ int wsum[4];
    int t = threadIdx.x;
    int v = (t < SCAN_NB) ? g_bsum[t] : 0;
    int inc = v;
    #pragma unroll
    for (int d = 1; d < 32; d <<= 1) {
        int u = __shfl_up_sync(0xffffffffu, inc, d);
        if ((t & 31) >= d) inc += u;
    }
    if ((t & 31) == 31) wsum[t >> 5] = inc;
    __syncthreads();
    if (t < 4) {
        int w = wsum[t];
        int wi = w;
        #pragma unroll
        for (int d = 1; d < 4; d <<= 1) {
            int u = __shfl_up_sync(0xfu, wi, d);
            if (t >= d) wi += u;
        }
        wsum[t] = wi - w;
    }
    __syncthreads();
    if (t < SCAN_NB) g_boff[t] = wsum[t >> 5] + (inc - v);
    if (t == 0) g_start[NTOT] = NNZ;
}
__global__ void k_scan3() {
    int i = blockIdx.x * blockDim.x + threadIdx.x;
    if (i >= NTOT) return;
    int s = g_start[i] + g_boff[i / SCAN_BS];
    g_start[i] = s;
    g_cursor[i] = s;
}
__global__ void k_scatter(const int* __restrict__ rows, const int* __restrict__ cols,
                          const float* __restrict__ vals) {
    int e = blockIdx.x * blockDim.x + threadIdx.x;
    if (e >= NNZ) return;
    int p = atomicAdd(&g_cursor[rows[e]], 1);
    g_edge[p] = make_int2(cols[e], __float_as_int(vals[e]));
}

// ---------------------------------------------------------------------------
// SpMM gather (proven fp32 version, packed edges)
// ---------------------------------------------------------------------------
__global__ void k_spmm_csr(int layer) {
    int r = blockIdx.x * (blockDim.x >> 5) + (threadIdx.x >> 5);
    if (r >= NTOT) return;
    int lane = threadIdx.x & 31;
    int s = g_start[r];
    int e = g_start[r + 1];
    const float* fb = g_final + (size_t)layer * D;
    float4 acc = make_float4(0.f, 0.f, 0.f, 0.f);
    for (int base = s; base < e; base += 32) {
        int idx = base + lane;
        int c = 0; float v = 0.f;
        if (idx < e) {
            int2 ed = g_edge[idx];
            c = ed.x; v = __int_as_float(ed.y);
        }
        int cnt = min(32, e - base);
        int j = 0;
        for (; j + 4 <= cnt; j += 4) {
            int   c0 = __shfl_sync(0xffffffffu, c, j + 0);
            int   c1 = __shfl_sync(0xffffffffu, c, j + 1);
            int   c2 = __shfl_sync(0xffffffffu, c, j + 2);
            int   c3 = __shfl_sync(0xffffffffu, c, j + 3);
            float v0 = __shfl_sync(0xffffffffu, v, j + 0);
            float v1 = __shfl_sync(0xffffffffu, v, j + 1);
            float v2 = __shfl_sync(0xffffffffu, v, j + 2);
            float v3 = __shfl_sync(0xffffffffu, v, j + 3);
            float4 x0 = ((const float4*)(fb + (size_t)c0 * FD))[lane];
            float4 x1 = ((const float4*)(fb + (size_t)c1 * FD))[lane];
            float4 x2 = ((const float4*)(fb + (size_t)c2 * FD))[lane];
            float4 x3 = ((const float4*)(fb + (size_t)c3 * FD))[lane];
            acc.x += v0 * x0.x + v1 * x1.x + v2 * x2.x + v3 * x3.x;
            acc.y += v0 * x0.y + v1 * x1.y + v2 * x2.y + v3 * x3.y;
            acc.z += v0 * x0.z + v1 * x1.z + v2 * x2.z + v3 * x3.z;
            acc.w += v0 * x0.w + v1 * x1.w + v2 * x2.w + v3 * x3.w;
        }
        for (; j < cnt; j++) {
            int   cj = __shfl_sync(0xffffffffu, c, j);
            float vj = __shfl_sync(0xffffffffu, v, j);
            float4 x = ((const float4*)(fb + (size_t)cj * FD))[lane];
            acc.x += vj * x.x; acc.y += vj * x.y;
            acc.z += vj * x.z; acc.w += vj * x.w;
        }
    }
    ((float4*)(g_Lx + (size_t)r * D))[lane] = acc;
}

// ---------------------------------------------------------------------------
// Persistent tensor-core dual-GEMM (R12 champion structure). B resident.
// smem: 2x34KB B + 4x17KB A (double-buffered S/P) = 136KB -> 1 CTA/SM.
// ---------------------------------------------------------------------------
__global__ void __launch_bounds__(NTHR) k_gemm_mma(const float* __restrict__ blin,
                                                   const float* __restrict__ bint,
                                                   int layer) {
    extern __shared__ char dsm[];
    __shared__ float sPart[MTILE][4];
    __shared__ float sBias[128];

    char* sBlin = dsm;
    char* sBint = dsm + BTILE_B;
    char* sA    = dsm + 2 * BTILE_B;
    uint32_t uBase = smem_u32(dsm);
    uint32_t uBlin = uBase;
    uint32_t uBint = uBase + BTILE_B;
    uint32_t uA    = uBase + 2 * BTILE_B;

    int tid = threadIdx.x;
    int wid = tid >> 5;
    int lane = tid & 31;
    int wm = wid & 1, wn = wid >> 1;
    int m0 = wm * 32, n0 = wn * 32;
    int g = lane >> 2, t4 = lane & 3;

    {
        const uint32_t* srcL = g_wimg + (size_t)(layer * 2 + 0) * 8192;
        const uint32_t* srcI = g_wimg + (size_t)(layer * 2 + 1) * 8192;
        for (int i = tid; i < 2048; i += NTHR) {
            int n = i >> 4;
            int jj = i & 15;
            *(uint4*)(sBlin + n * TPITCH_B + jj * 16) = ((const uint4*)(srcL + n * 64))[jj];
            *(uint4*)(sBint + n * TPITCH_B + jj * 16) = ((const uint4*)(srcI + n * 64))[jj];
        }
        if (tid < 128)
            sBias[tid] = __ldg(blin + (size_t)layer * D + tid) + __ldg(bint + (size_t)layer * D + tid);
    }

    int aRow = m0 + (lane & 15);
    uint32_t aOff0 = (uint32_t)(aRow * TPITCH_B + (lane >> 4) * 16);
    uint32_t aOff1 = aOff0 + 16 * TPITCH_B;
    int bRow = n0 + ((lane >> 4) << 3) + (lane & 7);
    uint32_t bOff0 = (uint32_t)(bRow * TPITCH_B + ((lane >> 3) & 1) * 16);
    uint32_t bOff1 = bOff0 + 16 * TPITCH_B;

    float4 rl[8], rf[8];

    auto load_regs = [&](int rbase) {
        #pragma unroll
        for (int i = 0; i < 4; i++) {
            int gg = tid + i * NTHR;
            int m = gg >> 4;
            int kg = (gg & 15) << 3;
            int r = rbase + m;
            if (r < NTOT) {
                const float4* lp4 = (const float4*)(g_Lx + (size_t)r * D + kg);
                const float4* fp4 = (const float4*)(g_final + (size_t)r * FD + (size_t)layer * D + kg);
                rl[2 * i + 0] = lp4[0]; rl[2 * i + 1] = lp4[1];
                rf[2 * i + 0] = fp4[0]; rf[2 * i + 1] = fp4[1];
            } else {
                float4 z = make_float4(0.f, 0.f, 0.f, 0.f);
                rl[2 * i] = z; rl[2 * i + 1] = z;
                rf[2 * i] = z; rf[2 * i + 1] = z;
            }
        }
    };
    auto convert_sts = [&](int buf) {
        char* sS = sA + buf * 2 * ATILE_B;
        char* sP = sS + ATILE_B;
        #pragma unroll
        for (int i = 0; i < 4; i++) {
            int gg = tid + i * NTHR;
            int m = gg >> 4;
            int kg = (gg & 15) << 3;
            float4 l0 = rl[2 * i], l1 = rl[2 * i + 1];
            float4 f0 = rf[2 * i], f1 = rf[2 * i + 1];
            uint32_t sv[4], pv[4];
            __half2 h;
            h = __floats2half2_rn(l0.x + f0.x, l0.y + f0.y); sv[0] = *(uint32_t*)&h;
            h = __floats2half2_rn(l0.z + f0.z, l0.w + f0.w); sv[1] = *(uint32_t*)&h;
            h = __floats2half2_rn(l1.x + f1.x, l1.y + f1.y); sv[2] = *(uint32_t*)&h;
            h = __floats2half2_rn(l1.z + f1.z, l1.w + f1.w); sv[3] = *(uint32_t*)&h;
            h = __floats2half2_rn(l0.x * f0.x, l0.y * f0.y); pv[0] = *(uint32_t*)&h;
            h = __floats2half2_rn(l0.z * f0.z, l0.w * f0.w); pv[1] = *(uint32_t*)&h;
            h = __floats2half2_rn(l1.x * f1.x, l1.y * f1.y); pv[2] = *(uint32_t*)&h;
            h = __floats2half2_rn(l1.z * f1.z, l1.w * f1.w); pv[3] = *(uint32_t*)&h;
            int off = m * TPITCH_B + kg * 2;
            *(uint4*)(sS + off) = make_uint4(sv[0], sv[1], sv[2], sv[3]);
            *(uint4*)(sP + off) = make_uint4(pv[0], pv[1], pv[2], pv[3]);
        }
    };

    load_regs(blockIdx.x * MTILE);
    convert_sts(0);
    __syncthreads();

    int buf = 0;
    for (int t = blockIdx.x; t * MTILE < NTOT; t += NSM) {
        int tn = t + NSM;
        bool have_next = (tn * MTILE < NTOT);
        if (have_next) load_regs(tn * MTILE);

        float c[2][4][4];
        #pragma unroll
        for (int mt = 0; mt < 2; mt++)
            #pragma unroll
            for (int j = 0; j < 4; j++)
                #pragma unroll
                for (int q = 0; q < 4; q++) c[mt][j][q] = 0.f;

        uint32_t uS = uA + buf * 2 * ATILE_B;
        #pragma unroll
        for (int phase = 0; phase < 2; phase++) {
            uint32_t uAcur = uS + phase * ATILE_B;
            uint32_t uBcur = phase ? uBint : uBlin;
            #pragma unroll
            for (int ks = 0; ks < 8; ks++) {
                uint32_t kb = (uint32_t)(ks * 32);
                uint32_t a[2][4], b[2][4];
                ldsm4(a[0], uAcur + aOff0 + kb);
                ldsm4(a[1], uAcur + aOff1 + kb);
                ldsm4(b[0], uBcur + bOff0 + kb);
                ldsm4(b[1], uBcur + bOff1 + kb);
                #pragma unroll
                for (int mt = 0; mt < 2; mt++) {
                    #pragma unroll
                    for (int j = 0; j < 4; j++) {
                        mma16816h(c[mt][j], a[mt],
                                  b[j >> 1][(j & 1) * 2], b[j >> 1][(j & 1) * 2 + 1]);
                    }
                }
            }
        }

        int rbase = t * MTILE;
        #pragma unroll
        for (int j = 0; j < 4; j++) {
            int col0 = n0 + j * 8 + 2 * t4;
            float b0 = sBias[col0];
            float b1 = sBias[col0 + 1];
            #pragma unroll
            for (int mt = 0; mt < 2; mt++) {
                c[mt][j][0] += b0; c[mt][j][1] += b1;
                c[mt][j][2] += b0; c[mt][j][3] += b1;
            }
        }
        #pragma unroll
        for (int mt = 0; mt < 2; mt++)
            #pragma unroll
            for (int j = 0; j < 4; j++)
                #pragma unroll
                for (int q = 0; q < 4; q++) {
                    float v = c[mt][j][q];
                    c[mt][j][q] = v > 0.f ? v : 0.01f * v;
                }

        float ss[2][2] = {{0.f, 0.f}, {0.f, 0.f}};
        #pragma unroll
        for (int mt = 0; mt < 2; mt++)
            #pragma unroll
            for (int j = 0; j < 4; j++) {
                ss[mt][0] += c[mt][j][0] * c[mt][j][0] + c[mt][j][1] * c[mt][j][1];
                ss[mt][1] += c[mt][j][2] * c[mt][j][2] + c[mt][j][3] * c[mt][j][3];
            }
        #pragma unroll
        for (int o = 1; o <= 2; o <<= 1) {
            #pragma unroll
            for (int mt = 0; mt < 2; mt++) {
                ss[mt][0] += __shfl_xor_sync(0xffffffffu, ss[mt][0], o);
                ss[mt][1] += __shfl_xor_sync(0xffffffffu, ss[mt][1], o);
            }
        }
        if (t4 == 0) {
            #pragma unroll
            for (int mt = 0; mt < 2; mt++) {
                sPart[m0 + mt * 16 + g][wn] = ss[mt][0];
                sPart[m0 + mt * 16 + g + 8][wn] = ss[mt][1];
            }
        }
        __syncthreads();

        #pragma unroll
        for (int mt = 0; mt < 2; mt++) {
            #pragma unroll
            for (int h = 0; h < 2; h++) {
                int row = m0 + mt * 16 + g + h * 8;
                float tot = sPart[row][0] + sPart[row][1] + sPart[row][2] + sPart[row][3];
                float scale = 1.0f / fmaxf(sqrtf(tot), 1e-12f);
                int rg = rbase + row;
                if (rg < NTOT) {
                    float* dst = g_final + (size_t)rg * FD + (size_t)(layer + 1) * D;
                    #pragma unroll
                    for (int j = 0; j < 4; j++) {
                        int col0 = n0 + j * 8 + 2 * t4;
                        *(float2*)(dst + col0) =
                            make_float2(c[mt][j][h * 2] * scale, c[mt][j][h * 2 + 1] * scale);
                    }
                }
            }
        }

        if (have_next) convert_sts(buf ^ 1);
        __syncthreads();
        buf ^= 1;
    }
}

// ---------------------------------------------------------------------------
// Final dot
// ---------------------------------------------------------------------------
__global__ void k_dot(const int* __restrict__ uIdx, const int* __restrict__ iIdx,
                      float* __restrict__ out) {
    int b = blockIdx.x * (blockDim.x >> 5) + (threadIdx.x >> 5);
    if (b >= BATCH) return;
    int lane = threadIdx.x & 31;
    int u = uIdx[b];
    int it = iIdx[b] + NUM_USERS;
    const float4* pu = (const float4*)(g_final + (size_t)u * FD);
    const float4* pi = (const float4*)(g_final + (size_t)it * FD);
    float s = 0.f;
    #pragma unroll
    for (int q = 0; q < 4; q++) {
        float4 a = pu[lane + 32 * q];
        float4 c = pi[lane + 32 * q];
        s += a.x * c.x + a.y * c.y + a.z * c.z + a.w * c.w;
    }
    #pragma unroll
    for (int o = 16; o > 0; o >>= 1)
        s += __shfl_xor_sync(0xffffffffu, s, o);
    if (lane == 0) out[b] = s;
}

// ---------------------------------------------------------------------------
extern "C" void kernel_launch(void* const* d_in, const int* in_sizes, int n_in,
                              void* d_out, int out_size) {
    const int*   userIdx = (const int*)d_in[0];
    const int*   itemIdx = (const int*)d_in[1];
    const int*   rows    = (const int*)d_in[2];
    const int*   cols    = (const int*)d_in[3];
    const float* vals    = (const float*)d_in[4];
    const float* uE      = (const float*)d_in[5];
    const float* iE      = (const float*)d_in[6];
    const float* Wlin    = (const float*)d_in[7];
    const float* blin    = (const float*)d_in[8];
    const float* Wint    = (const float*)d_in[9];
    const float* bint    = (const float*)d_in[10];
    float* out = (float*)d_out;

    // One-time host-side infra (no device memory involved)
    static cudaStream_t s2 = nullptr;
    static cudaEvent_t evFork = nullptr, evJoin = nullptr;
    if (s2 == nullptr) {
        cudaStreamCreateWithFlags(&s2, cudaStreamNonBlocking);
        cudaEventCreateWithFlags(&evFork, cudaEventDisableTiming);
        cudaEventCreateWithFlags(&evJoin, cudaEventDisableTiming);
    }

    const int smem_mma = 2 * BTILE_B + 4 * ATILE_B;  // 139264 B -> 1 CTA/SM
    cudaFuncSetAttribute(k_gemm_mma, cudaFuncAttributeMaxDynamicSharedMemorySize, smem_mma);

    // ---- Fork: CSR build on s2, feature/weight init on capture stream ----
    cudaEventRecord(evFork, 0);
    cudaStreamWaitEvent(s2, evFork, 0);

    k_zero_cnt<<<(NTOT + 255) / 256, 256, 0, s2>>>();
    k_count<<<(NNZ + 255) / 256, 256, 0, s2>>>(rows);
    k_scan1<<<SCAN_NB, 256, 0, s2>>>();
    k_scan2<<<1, 128, 0, s2>>>();
    k_scan3<<<(NTOT + 255) / 256, 256, 0, s2>>>();
    k_scatter<<<(NNZ + 255) / 256, 256, 0, s2>>>(rows, cols, vals);
    cudaEventRecord(evJoin, s2);

    const int vec_total = NTOT * (D / 4);
    k_init<<<(vec_total + 255) / 256, 256>>>(uE, iE);
    k_wconv<<<(3 * 2 * 128 * 64 + 255) / 256, 256>>>(Wlin, Wint);

    cudaStreamWaitEvent(0, evJoin, 0);   // join before layer loop

    for (int l = 0; l < NLAYERS; l++) {
        k_spmm_csr<<<(NTOT + 7) / 8, 256>>>(l);
        k_gemm_mma<<<NSM, NTHR, smem_mma>>>(blin, bint, l);
    }

    k_dot<<<(BATCH + 7) / 8, 256>>>(userIdx, itemIdx, out);
}